// round 7
// baseline (speedup 1.0000x reference)
#include <cuda_runtime.h>

// ChamferLossSplit: B=256, N=M=256, D=4, PID_MAX=5.
// Inputs: target f32 [B,N,4], reco f32 [B,M,4], in_pid i32 [B,N], out_pid i32 [B,M]
// Output: f32[2] = (mean per_nonzero, mean per_zero)
//
// Shuffle-ring, scalar math (R5 base). Each lane holds 8 target rows
// (rows lane+32k) so a warp holds all 256 rows; each warp owns 32 recos that
// circulate through the warp via shfl. Column mins do NOT travel: each step's
// 8-row partial (tr) is stored to an XOR-swizzled per-warp smem slab and
// gathered after the loop — removes the 32-deep serial SHFL chain.

#define NPTS 256
#define NWARP 8
#define RPL 8          // rows per lane
#define BIGC 1e18f     // sentinel coord for invalid points (4*BIGC^2 finite)
#define FULLMASK 0xffffffffu

__device__ __forceinline__ float warp_sum(float v) {
    #pragma unroll
    for (int o = 16; o; o >>= 1) v += __shfl_xor_sync(FULLMASK, v, o);
    return v;
}

__global__ void chamfer_init(float* out) {
    out[0] = 0.0f;
    out[1] = 0.0f;
}

__global__ __launch_bounds__(NPTS) void chamfer_kernel(
    const float4* __restrict__ target,
    const float4* __restrict__ reco,
    const int* __restrict__ in_pid,
    const int* __restrict__ out_pid,
    float* __restrict__ out,
    float invB)
{
    __shared__ float s_tr[NWARP][32][32];   // per-warp [step][lane^step] partial col mins
    __shared__ float s_row[NWARP * NPTS];   // per-warp partial row mins
    __shared__ float s_red[6][NWARP];       // cross-warp sum buffer

    const int b = blockIdx.x;
    const int i = threadIdx.x;
    const int lane = i & 31;
    const int wid  = i >> 5;
    const float INF = __int_as_float(0x7f800000);
    const int base = b * NPTS;

    // ---- own column j == i: load reco, mask, raw norm ----
    const float4 r0 = reco[base + i];
    const int my = (out_pid[base + i] != 0);
    float rn0_raw;
    {
        float c = r0.x * r0.x;
        c = fmaf(r0.y, r0.y, c); c = fmaf(r0.z, r0.z, c); c = fmaf(r0.w, r0.w, c);
        rn0_raw = sqrtf(c);
    }
    float4 rr = my ? r0 : make_float4(BIGC, BIGC, BIGC, BIGC);
    float rn = rr.x * rr.x;
    rn = fmaf(rr.y, rr.y, rn); rn = fmaf(rr.z, rr.z, rn); rn = fmaf(rr.w, rr.w, rn);

    // ---- load 8 rows per lane (rows lane+32k); k==wid is this thread's own row i ----
    float4 tv[RPL];
    float tn[RPL], rm[RPL];
    int   mx_self = 0;
    float t0n_self = 0.0f;
    #pragma unroll
    for (int k = 0; k < RPL; k++) {
        const int row = lane + 32 * k;
        const float4 t0 = target[base + row];
        const int m = (in_pid[base + row] != 0);
        if (k == wid) {  // row == i
            mx_self = m;
            float a = t0.x * t0.x;
            a = fmaf(t0.y, t0.y, a); a = fmaf(t0.z, t0.z, a); a = fmaf(t0.w, t0.w, a);
            t0n_self = sqrtf(a);
        }
        tv[k] = m ? t0 : make_float4(BIGC, BIGC, BIGC, BIGC);
        float a = tv[k].x * tv[k].x;
        a = fmaf(tv[k].y, tv[k].y, a);
        a = fmaf(tv[k].z, tv[k].z, a);
        a = fmaf(tv[k].w, tv[k].w, a);
        tn[k] = a;
        rm[k] = INF;
    }

    // ---- shuffle ring: 32 steps; reco travels, column-min partials go to smem ----
    const int src = (lane + 1) & 31;
    #pragma unroll 4
    for (int s = 0; s < 32; s++) {
        // prefetch next traveling reco (latency hidden under the math)
        const float nx = __shfl_sync(FULLMASK, rr.x, src);
        const float ny = __shfl_sync(FULLMASK, rr.y, src);
        const float nz = __shfl_sync(FULLMASK, rr.z, src);
        const float nw = __shfl_sync(FULLMASK, rr.w, src);
        const float nr = __shfl_sync(FULLMASK, rn,   src);

        float d2[RPL];
        #pragma unroll
        for (int k = 0; k < RPL; k++) {
            float dot = tv[k].x * rr.x;
            dot = fmaf(tv[k].y, rr.y, dot);
            dot = fmaf(tv[k].z, rr.z, dot);
            dot = fmaf(tv[k].w, rr.w, dot);
            d2[k] = fmaf(-2.0f, dot, tn[k]) + rn;
            rm[k] = fminf(rm[k], d2[k]);
        }
        const float m0 = fminf(d2[0], d2[1]);
        const float m1 = fminf(d2[2], d2[3]);
        const float m2 = fminf(d2[4], d2[5]);
        const float m3 = fminf(d2[6], d2[7]);
        const float tr = fminf(fminf(m0, m1), fminf(m2, m3));
        // XOR swizzle: STS conflict-free (lane^s distinct across lanes), and the
        // gather below is conflict-free too.
        s_tr[wid][s][lane ^ s] = tr;

        rr.x = nx; rr.y = ny; rr.z = nz; rr.w = nw; rn = nr;
    }

    // ---- combine per-warp partial row mins via smem slabs ----
    #pragma unroll
    for (int k = 0; k < RPL; k++)
        s_row[wid * NPTS + lane + 32 * k] = rm[k];
    __syncthreads();

    // Column min for column i: reco originating at lane o (=lane, warp wid) was
    // at lane l at step s=(o-l)&31, i.e. for step s it sat at l=(o-s)&31.
    float cmin = INF;
    #pragma unroll
    for (int s = 0; s < 32; s++) {
        const int l = (lane - s) & 31;
        cmin = fminf(cmin, s_tr[wid][s][l ^ s]);
    }

    float rowm = s_row[i];
    #pragma unroll
    for (int w = 1; w < NWARP; w++) rowm = fminf(rowm, s_row[w * NPTS + i]);

    // ---- per-thread contributions (sqrt clamped: dot-trick can round <0) ----
    float v[6];
    v[0] = mx_self ? 1.0f : 0.0f;                              // sum fx
    v[1] = my ? 1.0f : 0.0f;                                   // sum fy
    v[2] = mx_self ? sqrtf(fmaxf(rowm, 0.0f)) : 0.0f;          // sum_xy
    v[3] = my ? sqrtf(fmaxf(cmin, 0.0f)) : 0.0f;               // sum_yx
    v[4] = mx_self ? t0n_self : 0.0f;                          // fallback sum ||x||
    v[5] = my ? 0.0f : rn0_raw;                                // sum ||y|| zero-pid

    #pragma unroll
    for (int k = 0; k < 6; k++) {
        const float ws = warp_sum(v[k]);
        if (lane == 0) s_red[k][wid] = ws;
    }
    __syncthreads();

    if (i == 0) {
        float s[6];
        #pragma unroll
        for (int k = 0; k < 6; k++) {
            float acc = 0.0f;
            #pragma unroll
            for (int w = 0; w < NWARP; w++) acc += s_red[k][w];
            s[k] = acc;
        }
        const float sum_fx = s[0], sum_fy = s[1];
        const float sum_xy = s[2], sum_yx = s[3];
        const float sum_fb = s[4], sum_z  = s[5];

        const float n_in  = fmaxf(1.0f, sum_fx);
        const float n_out = fmaxf(1.0f, sum_fy);

        float per_nonzero;
        if (sum_fy == 0.0f) {
            per_nonzero = sum_fb / n_in;              // no valid reco
        } else if (sum_fx == 0.0f) {
            per_nonzero = 0.0f;                        // no valid target
        } else {
            per_nonzero = 0.5f * (sum_xy / n_out + sum_yx / n_in);
        }
        const float per_zero = sum_z / fmaxf(1.0f, (float)NPTS - sum_fy);

        atomicAdd(&out[0], per_nonzero * invB);
        atomicAdd(&out[1], per_zero * invB);
    }
}

extern "C" void kernel_launch(void* const* d_in, const int* in_sizes, int n_in,
                              void* d_out, int out_size)
{
    const float4* target  = (const float4*)d_in[0];
    const float4* reco    = (const float4*)d_in[1];
    const int*    in_pid  = (const int*)d_in[2];
    const int*    out_pid = (const int*)d_in[3];
    float*        out     = (float*)d_out;

    const int B = in_sizes[2] / NPTS;

    chamfer_init<<<1, 1>>>(out);
    chamfer_kernel<<<B, NPTS>>>(target, reco, in_pid, out_pid, out, 1.0f / (float)B);
}

// round 8
// speedup vs baseline: 1.0129x; 1.0129x over previous
#include <cuda_runtime.h>

// ChamferLossSplit: B=256, N=M=256, D=4, PID_MAX=5.
// Inputs: target f32 [B,N,4], reco f32 [B,M,4], in_pid i32 [B,N], out_pid i32 [B,M]
// Output: f32[2] = (mean per_nonzero, mean per_zero)
//
// Shuffle-ring, scalar math (R5 base). Each lane holds 8 target rows
// (rows lane+32k) so a warp holds all 256 rows; each warp owns 32 recos that
// circulate through the warp via shfl. Column mins do NOT travel: each step's
// 8-row partial (tr) is stored to an XOR-swizzled per-warp smem slab and
// gathered after the loop — removes the 32-deep serial SHFL chain.

#define NPTS 256
#define NWARP 8
#define RPL 8          // rows per lane
#define BIGC 1e18f     // sentinel coord for invalid points (4*BIGC^2 finite)
#define FULLMASK 0xffffffffu

__device__ __forceinline__ float warp_sum(float v) {
    #pragma unroll
    for (int o = 16; o; o >>= 1) v += __shfl_xor_sync(FULLMASK, v, o);
    return v;
}

__global__ void chamfer_init(float* out) {
    out[0] = 0.0f;
    out[1] = 0.0f;
}

__global__ __launch_bounds__(NPTS) void chamfer_kernel(
    const float4* __restrict__ target,
    const float4* __restrict__ reco,
    const int* __restrict__ in_pid,
    const int* __restrict__ out_pid,
    float* __restrict__ out,
    float invB)
{
    __shared__ float s_tr[NWARP][32][32];   // per-warp [step][lane^step] partial col mins
    __shared__ float s_row[NWARP * NPTS];   // per-warp partial row mins
    __shared__ float s_red[6][NWARP];       // cross-warp sum buffer

    const int b = blockIdx.x;
    const int i = threadIdx.x;
    const int lane = i & 31;
    const int wid  = i >> 5;
    const float INF = __int_as_float(0x7f800000);
    const int base = b * NPTS;

    // ---- own column j == i: load reco, mask, raw norm ----
    const float4 r0 = reco[base + i];
    const int my = (out_pid[base + i] != 0);
    float rn0_raw;
    {
        float c = r0.x * r0.x;
        c = fmaf(r0.y, r0.y, c); c = fmaf(r0.z, r0.z, c); c = fmaf(r0.w, r0.w, c);
        rn0_raw = sqrtf(c);
    }
    float4 rr = my ? r0 : make_float4(BIGC, BIGC, BIGC, BIGC);
    float rn = rr.x * rr.x;
    rn = fmaf(rr.y, rr.y, rn); rn = fmaf(rr.z, rr.z, rn); rn = fmaf(rr.w, rr.w, rn);

    // ---- load 8 rows per lane (rows lane+32k); k==wid is this thread's own row i ----
    float4 tv[RPL];
    float tn[RPL], rm[RPL];
    int   mx_self = 0;
    float t0n_self = 0.0f;
    #pragma unroll
    for (int k = 0; k < RPL; k++) {
        const int row = lane + 32 * k;
        const float4 t0 = target[base + row];
        const int m = (in_pid[base + row] != 0);
        if (k == wid) {  // row == i
            mx_self = m;
            float a = t0.x * t0.x;
            a = fmaf(t0.y, t0.y, a); a = fmaf(t0.z, t0.z, a); a = fmaf(t0.w, t0.w, a);
            t0n_self = sqrtf(a);
        }
        tv[k] = m ? t0 : make_float4(BIGC, BIGC, BIGC, BIGC);
        float a = tv[k].x * tv[k].x;
        a = fmaf(tv[k].y, tv[k].y, a);
        a = fmaf(tv[k].z, tv[k].z, a);
        a = fmaf(tv[k].w, tv[k].w, a);
        tn[k] = a;
        rm[k] = INF;
    }

    // ---- shuffle ring: 32 steps; reco travels, column-min partials go to smem ----
    const int src = (lane + 1) & 31;
    #pragma unroll 4
    for (int s = 0; s < 32; s++) {
        // prefetch next traveling reco (latency hidden under the math)
        const float nx = __shfl_sync(FULLMASK, rr.x, src);
        const float ny = __shfl_sync(FULLMASK, rr.y, src);
        const float nz = __shfl_sync(FULLMASK, rr.z, src);
        const float nw = __shfl_sync(FULLMASK, rr.w, src);
        const float nr = __shfl_sync(FULLMASK, rn,   src);

        float d2[RPL];
        #pragma unroll
        for (int k = 0; k < RPL; k++) {
            float dot = tv[k].x * rr.x;
            dot = fmaf(tv[k].y, rr.y, dot);
            dot = fmaf(tv[k].z, rr.z, dot);
            dot = fmaf(tv[k].w, rr.w, dot);
            d2[k] = fmaf(-2.0f, dot, tn[k]) + rn;
            rm[k] = fminf(rm[k], d2[k]);
        }
        const float m0 = fminf(d2[0], d2[1]);
        const float m1 = fminf(d2[2], d2[3]);
        const float m2 = fminf(d2[4], d2[5]);
        const float m3 = fminf(d2[6], d2[7]);
        const float tr = fminf(fminf(m0, m1), fminf(m2, m3));
        // XOR swizzle: STS conflict-free (lane^s distinct across lanes), and the
        // gather below is conflict-free too.
        s_tr[wid][s][lane ^ s] = tr;

        rr.x = nx; rr.y = ny; rr.z = nz; rr.w = nw; rn = nr;
    }

    // ---- combine per-warp partial row mins via smem slabs ----
    #pragma unroll
    for (int k = 0; k < RPL; k++)
        s_row[wid * NPTS + lane + 32 * k] = rm[k];
    __syncthreads();

    // Column min for column i: reco originating at lane o (=lane, warp wid) was
    // at lane l at step s=(o-l)&31, i.e. for step s it sat at l=(o-s)&31.
    float cmin = INF;
    #pragma unroll
    for (int s = 0; s < 32; s++) {
        const int l = (lane - s) & 31;
        cmin = fminf(cmin, s_tr[wid][s][l ^ s]);
    }

    float rowm = s_row[i];
    #pragma unroll
    for (int w = 1; w < NWARP; w++) rowm = fminf(rowm, s_row[w * NPTS + i]);

    // ---- per-thread contributions (sqrt clamped: dot-trick can round <0) ----
    float v[6];
    v[0] = mx_self ? 1.0f : 0.0f;                              // sum fx
    v[1] = my ? 1.0f : 0.0f;                                   // sum fy
    v[2] = mx_self ? sqrtf(fmaxf(rowm, 0.0f)) : 0.0f;          // sum_xy
    v[3] = my ? sqrtf(fmaxf(cmin, 0.0f)) : 0.0f;               // sum_yx
    v[4] = mx_self ? t0n_self : 0.0f;                          // fallback sum ||x||
    v[5] = my ? 0.0f : rn0_raw;                                // sum ||y|| zero-pid

    #pragma unroll
    for (int k = 0; k < 6; k++) {
        const float ws = warp_sum(v[k]);
        if (lane == 0) s_red[k][wid] = ws;
    }
    __syncthreads();

    if (i == 0) {
        float s[6];
        #pragma unroll
        for (int k = 0; k < 6; k++) {
            float acc = 0.0f;
            #pragma unroll
            for (int w = 0; w < NWARP; w++) acc += s_red[k][w];
            s[k] = acc;
        }
        const float sum_fx = s[0], sum_fy = s[1];
        const float sum_xy = s[2], sum_yx = s[3];
        const float sum_fb = s[4], sum_z  = s[5];

        const float n_in  = fmaxf(1.0f, sum_fx);
        const float n_out = fmaxf(1.0f, sum_fy);

        float per_nonzero;
        if (sum_fy == 0.0f) {
            per_nonzero = sum_fb / n_in;              // no valid reco
        } else if (sum_fx == 0.0f) {
            per_nonzero = 0.0f;                        // no valid target
        } else {
            per_nonzero = 0.5f * (sum_xy / n_out + sum_yx / n_in);
        }
        const float per_zero = sum_z / fmaxf(1.0f, (float)NPTS - sum_fy);

        atomicAdd(&out[0], per_nonzero * invB);
        atomicAdd(&out[1], per_zero * invB);
    }
}

extern "C" void kernel_launch(void* const* d_in, const int* in_sizes, int n_in,
                              void* d_out, int out_size)
{
    const float4* target  = (const float4*)d_in[0];
    const float4* reco    = (const float4*)d_in[1];
    const int*    in_pid  = (const int*)d_in[2];
    const int*    out_pid = (const int*)d_in[3];
    float*        out     = (float*)d_out;

    const int B = in_sizes[2] / NPTS;

    chamfer_init<<<1, 1>>>(out);
    chamfer_kernel<<<B, NPTS>>>(target, reco, in_pid, out_pid, out, 1.0f / (float)B);
}